// round 16
// baseline (speedup 1.0000x reference)
#include <cuda_runtime.h>

// Problem constants
#define T_STEPS 500
#define BATCH   1024
#define NDIM    256
#define ALPHA_F 0.995f   // 1 - 0.05/10
#define VTH_F   1.0f

#define TPB        256
#define C_BLOCKS   4                           // consumer blocks (first in grid)
#define ROWS_PB    40                          // 5 rows/warp x 8 warps (R7 shape)
#define ROWS_PW    5
#define N_ROWS     (T_STEPS * BATCH)           // 512000
#define P_BLOCKS   (N_ROWS / ROWS_PB)          // 12800 one-shot producer blocks

#define GROUP      4                           // consumer double-buffer depth

// Readiness protocol (no init kernel):
//   g_s word == 0x00000000 -> not ready (zero-init at load; re-poisoned by
//                             the consumer after each read for graph replays)
//   otherwise              -> word = ~bits(s). 0 unreachable (needs s = NaN).
__device__ unsigned g_s[T_STEPS * BATCH];      // 2 MB, L2-resident

__device__ __forceinline__ unsigned ld_relaxed_gpu_u32(const unsigned* p) {
    unsigned v;
    asm volatile("ld.relaxed.gpu.global.u32 %0, [%1];" : "=r"(v) : "l"(p) : "memory");
    return v;
}

// Forced wide load: asm volatile pins issue order, so all producer loads go
// out back-to-back with distinct live destinations (MLP=10). R15 failure mode
// was ptxas reusing dest regs (regs=32) and serializing the stream.
#define LDG128_NC(dst, ptr)                                            \
    asm volatile("ld.global.nc.v4.f32 {%0,%1,%2,%3}, [%4];"            \
                 : "=f"((dst).x), "=f"((dst).y), "=f"((dst).z), "=f"((dst).w) \
                 : "l"(ptr))

// ---------------------------------------------------------------------------
// Single fused kernel. Producers: one-shot, 40 rows, ZERO sync instructions.
// ---------------------------------------------------------------------------
__global__ void __launch_bounds__(TPB) lif_fused_kernel(
    const float* __restrict__ x,      // [T, B, N]
    const float* __restrict__ w,      // [N]
    float* __restrict__ out)          // [2, T, B]  (v then z)
{
    const int tid = threadIdx.x;

    if (blockIdx.x >= C_BLOCKS) {
        // ===== PRODUCER: 5 rows/warp, 10 forced-batched LDG.128 =====
        const int warp = tid >> 5;
        const int lane = tid & 31;
        const long long rbase =
            (long long)(blockIdx.x - C_BLOCKS) * ROWS_PB + warp * ROWS_PW;

        const float4* wv = reinterpret_cast<const float4*>(w);
        const float4 w0 = wv[lane];
        const float4 w1 = wv[lane + 32];

        const float4* x0 = reinterpret_cast<const float4*>(x + (rbase + 0) * NDIM);
        const float4* x1 = reinterpret_cast<const float4*>(x + (rbase + 1) * NDIM);
        const float4* x2 = reinterpret_cast<const float4*>(x + (rbase + 2) * NDIM);
        const float4* x3 = reinterpret_cast<const float4*>(x + (rbase + 3) * NDIM);
        const float4* x4 = reinterpret_cast<const float4*>(x + (rbase + 4) * NDIM);

        float4 a0, a1, a2, a3, a4, a5, a6, a7, a8, a9;
        LDG128_NC(a0, x0 + lane);
        LDG128_NC(a1, x0 + lane + 32);
        LDG128_NC(a2, x1 + lane);
        LDG128_NC(a3, x1 + lane + 32);
        LDG128_NC(a4, x2 + lane);
        LDG128_NC(a5, x2 + lane + 32);
        LDG128_NC(a6, x3 + lane);
        LDG128_NC(a7, x3 + lane + 32);
        LDG128_NC(a8, x4 + lane);
        LDG128_NC(a9, x4 + lane + 32);

        float acc[ROWS_PW];
        acc[0] = a0.x * w0.x + a0.y * w0.y + a0.z * w0.z + a0.w * w0.w
               + a1.x * w1.x + a1.y * w1.y + a1.z * w1.z + a1.w * w1.w;
        acc[1] = a2.x * w0.x + a2.y * w0.y + a2.z * w0.z + a2.w * w0.w
               + a3.x * w1.x + a3.y * w1.y + a3.z * w1.z + a3.w * w1.w;
        acc[2] = a4.x * w0.x + a4.y * w0.y + a4.z * w0.z + a4.w * w0.w
               + a5.x * w1.x + a5.y * w1.y + a5.z * w1.z + a5.w * w1.w;
        acc[3] = a6.x * w0.x + a6.y * w0.y + a6.z * w0.z + a6.w * w0.w
               + a7.x * w1.x + a7.y * w1.y + a7.z * w1.z + a7.w * w1.w;
        acc[4] = a8.x * w0.x + a8.y * w0.y + a8.z * w0.z + a8.w * w0.w
               + a9.x * w1.x + a9.y * w1.y + a9.z * w1.z + a9.w * w1.w;

        #pragma unroll
        for (int off = 16; off > 0; off >>= 1) {
            #pragma unroll
            for (int i = 0; i < ROWS_PW; ++i)
                acc[i] += __shfl_xor_sync(0xffffffffu, acc[i], off);
        }
        if (lane == 0) {
            #pragma unroll
            for (int i = 0; i < ROWS_PW; ++i)
                g_s[rbase + i] = ~__float_as_uint(acc[i]);   // != 0 always
        }
        // exit — no sync of any kind
    } else {
        // ===== CONSUMER: persistent, 4-deep double buffer, re-poisons =====
        const int b = blockIdx.x * TPB + tid;   // 0..1023
        float* __restrict__ vout = out;                               // [T, B]
        float* __restrict__ zout = out + (long long)T_STEPS * BATCH;  // [T, B]

        float v = 0.0f, z = 0.0f;
        unsigned cur[GROUP], nxt[GROUP];

        #pragma unroll
        for (int i = 0; i < GROUP; ++i)
            cur[i] = ld_relaxed_gpu_u32(&g_s[i * BATCH + b]);

        #pragma unroll 1
        for (int t = 0; t < T_STEPS; t += GROUP) {
            const int tn = t + GROUP;
            if (tn < T_STEPS) {
                #pragma unroll
                for (int i = 0; i < GROUP; ++i)
                    nxt[i] = ld_relaxed_gpu_u32(&g_s[(tn + i) * BATCH + b]);
            }

            #pragma unroll
            for (int i = 0; i < GROUP; ++i) {
                const long long idx = (long long)(t + i) * BATCH + b;
                while (cur[i] == 0u)                 // not ready yet
                    cur[i] = ld_relaxed_gpu_u32(&g_s[idx]);
                g_s[idx] = 0u;                       // re-poison for next replay

                const float s = __uint_as_float(~cur[i]);
                v = ALPHA_F * v + s - z;
                z = (v > VTH_F) ? 1.0f : 0.0f;
                vout[idx] = v;                       // same [T,B] layout as g_s
                zout[idx] = z;
            }

            #pragma unroll
            for (int i = 0; i < GROUP; ++i)
                cur[i] = nxt[i];
        }
    }
}

// ---------------------------------------------------------------------------
extern "C" void kernel_launch(void* const* d_in, const int* in_sizes, int n_in,
                              void* d_out, int out_size)
{
    const float* x = (const float*)d_in[0];   // [T, B, N] fp32
    const float* w = (const float*)d_in[1];   // [N] fp32
    float* out = (float*)d_out;               // [2, T, B] fp32

    lif_fused_kernel<<<C_BLOCKS + P_BLOCKS, TPB>>>(x, w, out);
}

// round 17
// speedup vs baseline: 2.1150x; 2.1150x over previous
#include <cuda_runtime.h>

// Problem constants
#define T_STEPS 500
#define BATCH   1024
#define NDIM    256
#define ALPHA_F 0.995f   // 1 - 0.05/10
#define VTH_F   1.0f

#define TPB        256
#define C_BLOCKS   4                           // consumer blocks (first in grid)
#define ROWS_PB    40                          // 5 rows/warp x 8 warps (R7 shape)
#define ROWS_PW    5
#define N_ROWS     (T_STEPS * BATCH)           // 512000
#define P_BLOCKS   (N_ROWS / ROWS_PB)          // 12800 one-shot producer blocks

#define CHUNK_T    20                          // consumer batch (20-deep arrays:
                                               // keeps kernel reg budget ~64 so the
                                               // producer's 10-load batch survives)

// Readiness protocol (no init kernel):
//   word == 0  -> not ready (zero-init at module load; consumer re-poisons
//                 after reading, so every graph replay starts poisoned)
//   word != 0  -> value = ~bits(s); 0 unreachable (would need s = NaN).
__device__ unsigned g_s[T_STEPS * BATCH];      // 2 MB, L2-resident

__device__ __forceinline__ unsigned ld_relaxed_gpu_u32(const unsigned* p) {
    unsigned v;
    asm volatile("ld.relaxed.gpu.global.u32 %0, [%1];" : "=r"(v) : "l"(p) : "memory");
    return v;
}

// ---------------------------------------------------------------------------
// Single fused kernel. Producer = R7 body minus fence/atomic.
// ---------------------------------------------------------------------------
__global__ void __launch_bounds__(TPB) lif_fused_kernel(
    const float* __restrict__ x,      // [T, B, N]
    const float* __restrict__ w,      // [N]
    float* __restrict__ out)          // [2, T, B]  (v then z)
{
    const int tid = threadIdx.x;

    if (blockIdx.x >= C_BLOCKS) {
        // ===== PRODUCER (R7 body: 5 rows/warp, 10 batched float4 loads) =====
        const int warp = tid >> 5;
        const int lane = tid & 31;
        const long long rbase =
            (long long)(blockIdx.x - C_BLOCKS) * ROWS_PB + warp * ROWS_PW;

        const float4* wv = reinterpret_cast<const float4*>(w);
        const float4 w0 = wv[lane];
        const float4 w1 = wv[lane + 32];

        float4 a[2 * ROWS_PW];
        #pragma unroll
        for (int i = 0; i < ROWS_PW; ++i) {
            const float4* xr =
                reinterpret_cast<const float4*>(x + (rbase + i) * NDIM);
            a[2 * i]     = xr[lane];
            a[2 * i + 1] = xr[lane + 32];
        }

        float acc[ROWS_PW];
        #pragma unroll
        for (int i = 0; i < ROWS_PW; ++i) {
            const float4 p0 = a[2 * i], p1 = a[2 * i + 1];
            acc[i] = p0.x * w0.x + p0.y * w0.y + p0.z * w0.z + p0.w * w0.w
                   + p1.x * w1.x + p1.y * w1.y + p1.z * w1.z + p1.w * w1.w;
        }
        #pragma unroll
        for (int off = 16; off > 0; off >>= 1) {
            #pragma unroll
            for (int i = 0; i < ROWS_PW; ++i)
                acc[i] += __shfl_xor_sync(0xffffffffu, acc[i], off);
        }
        if (lane == 0) {
            #pragma unroll
            for (int i = 0; i < ROWS_PW; ++i)
                g_s[rbase + i] = ~__float_as_uint(acc[i]);   // != 0 always
        }

        __syncthreads();   // kept from R7 (same scheduling regions); no fence,
                           // no atomic — the stored value itself is the flag.
    } else {
        // ===== CONSUMER (R7 structure, 20-deep arrays, sentinel spin) =====
        const int b = blockIdx.x * TPB + tid;   // 0..1023
        float* __restrict__ vout = out;                               // [T, B]
        float* __restrict__ zout = out + (long long)T_STEPS * BATCH;  // [T, B]

        float v = 0.0f, z = 0.0f;

        #pragma unroll 1
        for (int c = 0; c < T_STEPS / CHUNK_T; ++c) {
            const int tbase = c * CHUNK_T;

            // batch-issue 20 polls (keeps 20 live regs -> kernel budget ~64)
            unsigned bits[CHUNK_T];
            #pragma unroll
            for (int i = 0; i < CHUNK_T; ++i)
                bits[i] = ld_relaxed_gpu_u32(&g_s[(tbase + i) * BATCH + b]);

            // verify / spin per word, then re-poison for the next replay
            #pragma unroll
            for (int i = 0; i < CHUNK_T; ++i) {
                const long long idx = (long long)(tbase + i) * BATCH + b;
                while (bits[i] == 0u)
                    bits[i] = ld_relaxed_gpu_u32(&g_s[idx]);
                g_s[idx] = 0u;
            }

            #pragma unroll
            for (int i = 0; i < CHUNK_T; ++i) {
                const float s = __uint_as_float(~bits[i]);
                v = ALPHA_F * v + s - z;
                z = (v > VTH_F) ? 1.0f : 0.0f;
                const long long idx = (long long)(tbase + i) * BATCH + b;
                vout[idx] = v;
                zout[idx] = z;
            }
        }
    }
}

// ---------------------------------------------------------------------------
extern "C" void kernel_launch(void* const* d_in, const int* in_sizes, int n_in,
                              void* d_out, int out_size)
{
    const float* x = (const float*)d_in[0];   // [T, B, N] fp32
    const float* w = (const float*)d_in[1];   // [N] fp32
    float* out = (float*)d_out;               // [2, T, B] fp32

    lif_fused_kernel<<<C_BLOCKS + P_BLOCKS, TPB>>>(x, w, out);
}